// round 3
// baseline (speedup 1.0000x reference)
#include <cuda_runtime.h>

#define B_ 32
#define T_ 128
#define N_ 128
#define M_ 64
#define NT_ 192

// ---------------- device scratch (no allocations allowed) ----------------
__device__ float g_V[B_ * N_ * N_];
__device__ float g_v[B_ * N_];
__device__ float g_w[B_ * N_];
__device__ float g_VF[B_ * N_ * NT_];
__device__ float g_Qxx[B_ * N_ * N_];
__device__ float g_Qu[B_ * M_ * NT_];   // rows 0..63: cols 0..127 = Qux, 128..191 = Quu
__device__ float g_qhat[B_ * NT_];
__device__ float g_K[(size_t)T_ * B_ * M_ * N_];
__device__ float g_k[T_ * B_ * M_];

#define FMA16(a, bq)                                                                   \
    acc[0][0] += a.x * bq.x; acc[0][1] += a.x * bq.y; acc[0][2] += a.x * bq.z; acc[0][3] += a.x * bq.w; \
    acc[1][0] += a.y * bq.x; acc[1][1] += a.y * bq.y; acc[1][2] += a.y * bq.z; acc[1][3] += a.y * bq.w; \
    acc[2][0] += a.z * bq.x; acc[2][1] += a.z * bq.y; acc[2][2] += a.z * bq.z; acc[2][3] += a.z * bq.w; \
    acc[3][0] += a.w * bq.x; acc[3][1] += a.w * bq.y; acc[3][2] += a.w * bq.z; acc[3][3] += a.w * bq.w;

// ---------------- init ----------------
__global__ void kzero() {
    int idx = blockIdx.x * 256 + threadIdx.x;
    if (idx < B_ * N_ * N_) g_V[idx] = 0.0f;
    if (idx < B_ * N_) g_v[idx] = 0.0f;
}

// ---------------- k1: VF = V @ [A|B]  (uses V symmetry), w = V c + v ----------------
__global__ __launch_bounds__(256) void k1_VF(const float* __restrict__ A,
                                             const float* __restrict__ Bm,
                                             const float* __restrict__ c1, int t) {
    int b = blockIdx.y;
    int bx = blockIdx.x;
    int tid = threadIdx.x;
    const float* Vb = g_V + b * N_ * N_;
    size_t bt = (size_t)b * T_ + t;

    if (bx == 6) {  // w = V c + v  (V symmetric -> coalesced column read)
        __shared__ float cs[128];
        if (tid < 128) cs[tid] = c1[bt * 128 + tid];
        __syncthreads();
        if (tid < 128) {
            float acc = g_v[b * 128 + tid];
#pragma unroll 8
            for (int m = 0; m < 128; m++) acc += Vb[m * 128 + tid] * cs[m];
            g_w[b * 128 + tid] = acc;
        }
        return;
    }

    int tr = bx / 3, tc = bx % 3;
    int rb = tr * 64, cb = tc * 64;
    const float* Fsrc; int ldF, coff;
    if (cb < 128) { Fsrc = A + bt * (size_t)(N_ * N_); ldF = 128; coff = cb; }
    else          { Fsrc = Bm + bt * (size_t)(N_ * M_); ldF = 64;  coff = 0;  }

    __shared__ float As[16][64];
    __shared__ float Bs[16][64];
    int tx = tid & 15, ty = tid >> 4;
    float acc[4][4] = {};

    for (int kb = 0; kb < 8; kb++) {
        int k = kb * 16 + ty;
        // V symmetric: V[row][k] == V[k][row]
        *(float4*)&As[ty][tx * 4] = *(const float4*)(Vb + k * 128 + rb + tx * 4);
        *(float4*)&Bs[ty][tx * 4] = *(const float4*)(Fsrc + (size_t)k * ldF + coff + tx * 4);
        __syncthreads();
#pragma unroll
        for (int kk = 0; kk < 16; kk++) {
            float4 a = *(float4*)&As[kk][ty * 4];
            float4 bq = *(float4*)&Bs[kk][tx * 4];
            FMA16(a, bq)
        }
        __syncthreads();
    }
    float* outp = g_VF + b * N_ * NT_;
#pragma unroll
    for (int i = 0; i < 4; i++) {
        *(float4*)(outp + (rb + ty * 4 + i) * NT_ + cb + tx * 4) =
            make_float4(acc[i][0], acc[i][1], acc[i][2], acc[i][3]);
    }
}

// ---------------- k2: Qxx = Qxx + A^T VF ; [Qux|Quu] = Q_u + B^T VF ; qhat ----------------
__global__ __launch_bounds__(256) void k2_Qhat(const float* __restrict__ A,
                                               const float* __restrict__ Bm,
                                               const float* __restrict__ Q,
                                               const float* __restrict__ p, int t) {
    int b = blockIdx.y, bx = blockIdx.x, tid = threadIdx.x;
    size_t bt = (size_t)b * T_ + t;

    if (bx == 7) {  // qhat = p + F^T w
        __shared__ float ws[128];
        if (tid < 128) ws[tid] = g_w[b * 128 + tid];
        __syncthreads();
        if (tid < 192) {
            float acc = p[bt * NT_ + tid];
            if (tid < 128) {
                const float* Ab = A + bt * (size_t)(N_ * N_);
#pragma unroll 4
                for (int n = 0; n < 128; n++) acc += Ab[n * 128 + tid] * ws[n];
            } else {
                const float* Bb = Bm + bt * (size_t)(N_ * M_);
                int j = tid - 128;
#pragma unroll 4
                for (int n = 0; n < 128; n++) acc += Bb[n * 64 + j] * ws[n];
            }
            g_qhat[b * NT_ + tid] = acc;
        }
        return;
    }

    bool isQxx = bx < 4;
    int ib, jb; const float* Asrc; int lda, aoff;
    if (isQxx) { ib = (bx >> 1) * 64; jb = (bx & 1) * 64; Asrc = A + bt * (size_t)(N_ * N_); lda = 128; aoff = ib; }
    else       { ib = 0; jb = (bx - 4) * 64; Asrc = Bm + bt * (size_t)(N_ * M_); lda = 64; aoff = 0; }

    __shared__ float As[16][64];
    __shared__ float Bs[16][64];
    int tx = tid & 15, ty = tid >> 4;
    const float* VFb = g_VF + b * N_ * NT_;
    float acc[4][4] = {};

    for (int kb = 0; kb < 8; kb++) {
        int k = kb * 16 + ty;
        *(float4*)&As[ty][tx * 4] = *(const float4*)(Asrc + (size_t)k * lda + aoff + tx * 4);
        *(float4*)&Bs[ty][tx * 4] = *(const float4*)(VFb + k * NT_ + jb + tx * 4);
        __syncthreads();
#pragma unroll
        for (int kk = 0; kk < 16; kk++) {
            float4 a = *(float4*)&As[kk][ty * 4];
            float4 bq = *(float4*)&Bs[kk][tx * 4];
            FMA16(a, bq)
        }
        __syncthreads();
    }

    const float* Qb = Q + bt * (size_t)(NT_ * NT_);
    if (isQxx) {
        float* outp = g_Qxx + b * N_ * N_;
#pragma unroll
        for (int i = 0; i < 4; i++) {
            int r = ib + ty * 4 + i, cc = jb + tx * 4;
            float4 q4 = *(const float4*)(Qb + (size_t)r * NT_ + cc);
            *(float4*)(outp + r * N_ + cc) =
                make_float4(acc[i][0] + q4.x, acc[i][1] + q4.y, acc[i][2] + q4.z, acc[i][3] + q4.w);
        }
    } else {
        float* outp = g_Qu + b * M_ * NT_;
#pragma unroll
        for (int i = 0; i < 4; i++) {
            int r = ty * 4 + i, cc = jb + tx * 4;
            float4 q4 = *(const float4*)(Qb + (size_t)(128 + r) * NT_ + cc);
            *(float4*)(outp + r * NT_ + cc) =
                make_float4(acc[i][0] + q4.x, acc[i][1] + q4.y, acc[i][2] + q4.z, acc[i][3] + q4.w);
        }
    }
}

// ---------------- k3: Cholesky(Quu) + 129-RHS solve -> K, k, vn ----------------
__global__ __launch_bounds__(256) void k3_solve(int t) {
    int b = blockIdx.x, tid = threadIdx.x;
    __shared__ float sL[64 * 65];
    __shared__ float sInvD[64];
    __shared__ float sk[64];
    const float* Qub = g_Qu + b * M_ * NT_;

    for (int idx = tid; idx < 64 * 64; idx += 256) {
        int i = idx >> 6, j = idx & 63;
        sL[i * 65 + j] = Qub[i * NT_ + 128 + j];
    }
    __syncthreads();

    // lower Cholesky in place; diag kept as reciprocal sqrt in sInvD
    for (int i = 0; i < 64; i++) {
        float d = sL[i * 65 + i];
        float dinv = rsqrtf(d);
        if (tid == 0) sInvD[i] = dinv;
        if (tid < 63 - i) {
            int j = i + 1 + tid;
            sL[j * 65 + i] *= dinv;
        }
        __syncthreads();
        int rem = 63 - i;
        for (int idx = tid; idx < rem * rem; idx += 256) {
            int r = idx / rem, cc = idx - r * rem;
            int j = i + 1 + r, c2 = i + 1 + cc;
            if (c2 <= j) sL[j * 65 + c2] -= sL[j * 65 + i] * sL[c2 * 65 + i];
        }
        __syncthreads();
    }

    // one lane per RHS column: cols 0..127 = Qux, col 128 = qu
    int c = tid;
    if (c < 129) {
        float y[64];
        for (int j = 0; j < 64; j++) {
            float rhs = (c < 128) ? Qub[j * NT_ + c] : g_qhat[b * NT_ + 128 + j];
            float s0 = 0.f, s1 = 0.f;
            int i = 0;
            for (; i + 1 < j; i += 2) {
                s0 += sL[j * 65 + i] * y[i];
                s1 += sL[j * 65 + i + 1] * y[i + 1];
            }
            if (i < j) s0 += sL[j * 65 + i] * y[i];
            y[j] = (rhs - s0 - s1) * sInvD[j];
        }
        for (int j = 63; j >= 0; j--) {
            float s0 = 0.f, s1 = 0.f;
            int i = j + 1;
            for (; i + 1 < 64; i += 2) {
                s0 += sL[i * 65 + j] * y[i];
                s1 += sL[(i + 1) * 65 + j] * y[i + 1];
            }
            if (i < 64) s0 += sL[i * 65 + j] * y[i];
            y[j] = (y[j] - s0 - s1) * sInvD[j];
        }
        if (c < 128) {
            float* Kb = g_K + ((size_t)t * B_ + b) * (M_ * N_);
            for (int j = 0; j < 64; j++) Kb[j * 128 + c] = -y[j];
        } else {
            float* kb = g_k + ((size_t)t * B_ + b) * M_;
            for (int j = 0; j < 64; j++) { kb[j] = -y[j]; sk[j] = -y[j]; }
        }
    }
    __syncthreads();

    // vn = qx + Qux^T k
    if (tid < 128) {
        float acc = g_qhat[b * NT_ + tid];
#pragma unroll 4
        for (int m = 0; m < 64; m++) acc += Qub[m * NT_ + tid] * sk[m];
        g_v[b * 128 + tid] = acc;
    }
}

// ---------------- k4: Vn = Qxx + Qux^T @ K ----------------
__global__ __launch_bounds__(256) void k4_Vn(int t) {
    int b = blockIdx.y, bx = blockIdx.x, tid = threadIdx.x;
    int ib = (bx >> 1) * 64, jb = (bx & 1) * 64;
    const float* Qub = g_Qu + b * M_ * NT_;
    const float* Kb = g_K + ((size_t)t * B_ + b) * (M_ * N_);
    __shared__ float As[16][64];
    __shared__ float Bs[16][64];
    int tx = tid & 15, ty = tid >> 4;
    float acc[4][4] = {};

    for (int kb = 0; kb < 4; kb++) {
        int k = kb * 16 + ty;
        *(float4*)&As[ty][tx * 4] = *(const float4*)(Qub + k * NT_ + ib + tx * 4);
        *(float4*)&Bs[ty][tx * 4] = *(const float4*)(Kb + k * 128 + jb + tx * 4);
        __syncthreads();
#pragma unroll
        for (int kk = 0; kk < 16; kk++) {
            float4 a = *(float4*)&As[kk][ty * 4];
            float4 bq = *(float4*)&Bs[kk][tx * 4];
            FMA16(a, bq)
        }
        __syncthreads();
    }
    const float* Qxxb = g_Qxx + b * N_ * N_;
    float* Vb = g_V + b * N_ * N_;
#pragma unroll
    for (int i = 0; i < 4; i++) {
        int r = ib + ty * 4 + i, cc = jb + tx * 4;
        float4 q4 = *(const float4*)(Qxxb + r * N_ + cc);
        *(float4*)(Vb + r * N_ + cc) =
            make_float4(acc[i][0] + q4.x, acc[i][1] + q4.y, acc[i][2] + q4.z, acc[i][3] + q4.w);
    }
}

// ---------------- forward rollout ----------------
__global__ __launch_bounds__(256) void kfwd(const float* __restrict__ A,
                                            const float* __restrict__ Bm,
                                            const float* __restrict__ c1,
                                            const float* __restrict__ xinit,
                                            float* __restrict__ out) {
    int b = blockIdx.x, tid = threadIdx.x;
    int warp = tid >> 5, lane = tid & 31;
    __shared__ float sx[128], su[64], sxn[128];
    if (tid < 128) sx[tid] = xinit[b * 128 + tid];
    __syncthreads();

    for (int t = 0; t < 128; t++) {
        size_t bt = (size_t)b * T_ + t;
        const float* Kb = g_K + ((size_t)t * B_ + b) * (M_ * N_);
        const float* kb = g_k + ((size_t)t * B_ + b) * M_;
        for (int r = warp; r < 64; r += 8) {
            const float* kr = Kb + r * 128;
            float s = kr[lane] * sx[lane] + kr[32 + lane] * sx[32 + lane]
                    + kr[64 + lane] * sx[64 + lane] + kr[96 + lane] * sx[96 + lane];
#pragma unroll
            for (int o = 16; o; o >>= 1) s += __shfl_down_sync(0xffffffffu, s, o);
            if (lane == 0) su[r] = s + kb[r];
        }
        if (tid < 128) out[bt * NT_ + tid] = sx[tid];
        __syncthreads();
        if (tid < 64) out[bt * NT_ + 128 + tid] = su[tid];

        const float* Ab = A + bt * (size_t)(N_ * N_);
        const float* Bb = Bm + bt * (size_t)(N_ * M_);
        for (int r = warp; r < 128; r += 8) {
            const float* ar = Ab + r * 128;
            const float* br = Bb + r * 64;
            float s = ar[lane] * sx[lane] + ar[32 + lane] * sx[32 + lane]
                    + ar[64 + lane] * sx[64 + lane] + ar[96 + lane] * sx[96 + lane]
                    + br[lane] * su[lane] + br[32 + lane] * su[32 + lane];
#pragma unroll
            for (int o = 16; o; o >>= 1) s += __shfl_down_sync(0xffffffffu, s, o);
            if (lane == 0) sxn[r] = s + c1[bt * 128 + r];
        }
        __syncthreads();
        if (tid < 128) sx[tid] = sxn[tid];
        __syncthreads();
    }
}

// ---------------- launch ----------------
extern "C" void kernel_launch(void* const* d_in, const int* in_sizes, int n_in,
                              void* d_out, int out_size) {
    const float *A = 0, *Bm = 0, *c1 = 0, *Q = 0, *p = 0, *xinit = 0;
    for (int i = 0; i < n_in; i++) {
        switch (in_sizes[i]) {
            case 67108864:  A = (const float*)d_in[i]; break;      // 32*128*128*128
            case 33554432:  Bm = (const float*)d_in[i]; break;     // 32*128*128*64
            case 524288:    c1 = (const float*)d_in[i]; break;     // 32*128*128
            case 150994944: Q = (const float*)d_in[i]; break;      // 32*128*192*192
            case 786432:    p = (const float*)d_in[i]; break;      // 32*128*192
            case 4096:      xinit = (const float*)d_in[i]; break;  // 32*128
        }
    }
    float* out = (float*)d_out;

    kzero<<<(B_ * N_ * N_ + 255) / 256, 256>>>();
    for (int t = T_ - 1; t >= 0; t--) {
        k1_VF<<<dim3(7, B_), 256>>>(A, Bm, c1, t);
        k2_Qhat<<<dim3(8, B_), 256>>>(A, Bm, Q, p, t);
        k3_solve<<<B_, 256>>>(t);
        k4_Vn<<<dim3(4, B_), 256>>>(t);
    }
    kfwd<<<B_, 256>>>(A, Bm, c1, xinit, out);
}

// round 4
// speedup vs baseline: 1.4861x; 1.4861x over previous
#include <cuda_runtime.h>

#define B_ 32
#define T_ 128
#define N_ 128
#define M_ 64
#define NT_ 192

// ---------------- device scratch (no allocations allowed) ----------------
__device__ float g_V[B_ * N_ * N_];
__device__ float g_v[B_ * N_];
__device__ float g_w[B_ * N_];
__device__ float g_VF[B_ * N_ * NT_];
__device__ float g_Qxx[B_ * N_ * N_];
__device__ float g_Qu[B_ * M_ * NT_];   // rows 0..63: cols 0..127 = Qux, 128..191 = Quu
__device__ float g_qhat[B_ * NT_];
__device__ float g_K[(size_t)T_ * B_ * M_ * N_];
__device__ float g_k[T_ * B_ * M_];

#define FMA16(a, bq)                                                                   \
    acc[0][0] += a.x * bq.x; acc[0][1] += a.x * bq.y; acc[0][2] += a.x * bq.z; acc[0][3] += a.x * bq.w; \
    acc[1][0] += a.y * bq.x; acc[1][1] += a.y * bq.y; acc[1][2] += a.y * bq.z; acc[1][3] += a.y * bq.w; \
    acc[2][0] += a.z * bq.x; acc[2][1] += a.z * bq.y; acc[2][2] += a.z * bq.z; acc[2][3] += a.z * bq.w; \
    acc[3][0] += a.w * bq.x; acc[3][1] += a.w * bq.y; acc[3][2] += a.w * bq.z; acc[3][3] += a.w * bq.w;

// ---------------- init ----------------
__global__ void kzero() {
    int idx = blockIdx.x * 256 + threadIdx.x;
    if (idx < B_ * N_ * N_) g_V[idx] = 0.0f;
    if (idx < B_ * N_) g_v[idx] = 0.0f;
}

// ---------------- k1: VF = V @ [A|B]  (uses V symmetry), w = V c + v ----------------
__global__ __launch_bounds__(256) void k1_VF(const float* __restrict__ A,
                                             const float* __restrict__ Bm,
                                             const float* __restrict__ c1, int t) {
    int b = blockIdx.y;
    int bx = blockIdx.x;
    int tid = threadIdx.x;
    const float* Vb = g_V + b * N_ * N_;
    size_t bt = (size_t)b * T_ + t;

    if (bx == 6) {  // w = V c + v  (V symmetric -> coalesced column read)
        __shared__ float cs[128];
        if (tid < 128) cs[tid] = c1[bt * 128 + tid];
        __syncthreads();
        if (tid < 128) {
            float acc = g_v[b * 128 + tid];
#pragma unroll 8
            for (int m = 0; m < 128; m++) acc += Vb[m * 128 + tid] * cs[m];
            g_w[b * 128 + tid] = acc;
        }
        return;
    }

    int tr = bx / 3, tc = bx % 3;
    int rb = tr * 64, cb = tc * 64;
    const float* Fsrc; int ldF, coff;
    if (cb < 128) { Fsrc = A + bt * (size_t)(N_ * N_); ldF = 128; coff = cb; }
    else          { Fsrc = Bm + bt * (size_t)(N_ * M_); ldF = 64;  coff = 0;  }

    __shared__ float As[16][64];
    __shared__ float Bs[16][64];
    int tx = tid & 15, ty = tid >> 4;
    float acc[4][4] = {};

    for (int kb = 0; kb < 8; kb++) {
        int k = kb * 16 + ty;
        // V symmetric: V[row][k] == V[k][row]
        *(float4*)&As[ty][tx * 4] = *(const float4*)(Vb + k * 128 + rb + tx * 4);
        *(float4*)&Bs[ty][tx * 4] = *(const float4*)(Fsrc + (size_t)k * ldF + coff + tx * 4);
        __syncthreads();
#pragma unroll
        for (int kk = 0; kk < 16; kk++) {
            float4 a = *(float4*)&As[kk][ty * 4];
            float4 bq = *(float4*)&Bs[kk][tx * 4];
            FMA16(a, bq)
        }
        __syncthreads();
    }
    float* outp = g_VF + b * N_ * NT_;
#pragma unroll
    for (int i = 0; i < 4; i++) {
        *(float4*)(outp + (rb + ty * 4 + i) * NT_ + cb + tx * 4) =
            make_float4(acc[i][0], acc[i][1], acc[i][2], acc[i][3]);
    }
}

// ---------------- k2: Qxx = Qxx + A^T VF ; [Qux|Quu] = Q_u + B^T VF ; qhat ----------------
__global__ __launch_bounds__(256) void k2_Qhat(const float* __restrict__ A,
                                               const float* __restrict__ Bm,
                                               const float* __restrict__ Q,
                                               const float* __restrict__ p, int t) {
    int b = blockIdx.y, bx = blockIdx.x, tid = threadIdx.x;
    size_t bt = (size_t)b * T_ + t;

    if (bx == 7) {  // qhat = p + F^T w
        __shared__ float ws[128];
        if (tid < 128) ws[tid] = g_w[b * 128 + tid];
        __syncthreads();
        if (tid < 192) {
            float acc = p[bt * NT_ + tid];
            if (tid < 128) {
                const float* Ab = A + bt * (size_t)(N_ * N_);
#pragma unroll 4
                for (int n = 0; n < 128; n++) acc += Ab[n * 128 + tid] * ws[n];
            } else {
                const float* Bb = Bm + bt * (size_t)(N_ * M_);
                int j = tid - 128;
#pragma unroll 4
                for (int n = 0; n < 128; n++) acc += Bb[n * 64 + j] * ws[n];
            }
            g_qhat[b * NT_ + tid] = acc;
        }
        return;
    }

    bool isQxx = bx < 4;
    int ib, jb; const float* Asrc; int lda, aoff;
    if (isQxx) { ib = (bx >> 1) * 64; jb = (bx & 1) * 64; Asrc = A + bt * (size_t)(N_ * N_); lda = 128; aoff = ib; }
    else       { ib = 0; jb = (bx - 4) * 64; Asrc = Bm + bt * (size_t)(N_ * M_); lda = 64; aoff = 0; }

    __shared__ float As[16][64];
    __shared__ float Bs[16][64];
    int tx = tid & 15, ty = tid >> 4;
    const float* VFb = g_VF + b * N_ * NT_;
    float acc[4][4] = {};

    for (int kb = 0; kb < 8; kb++) {
        int k = kb * 16 + ty;
        *(float4*)&As[ty][tx * 4] = *(const float4*)(Asrc + (size_t)k * lda + aoff + tx * 4);
        *(float4*)&Bs[ty][tx * 4] = *(const float4*)(VFb + k * NT_ + jb + tx * 4);
        __syncthreads();
#pragma unroll
        for (int kk = 0; kk < 16; kk++) {
            float4 a = *(float4*)&As[kk][ty * 4];
            float4 bq = *(float4*)&Bs[kk][tx * 4];
            FMA16(a, bq)
        }
        __syncthreads();
    }

    const float* Qb = Q + bt * (size_t)(NT_ * NT_);
    if (isQxx) {
        float* outp = g_Qxx + b * N_ * N_;
#pragma unroll
        for (int i = 0; i < 4; i++) {
            int r = ib + ty * 4 + i, cc = jb + tx * 4;
            float4 q4 = *(const float4*)(Qb + (size_t)r * NT_ + cc);
            *(float4*)(outp + r * N_ + cc) =
                make_float4(acc[i][0] + q4.x, acc[i][1] + q4.y, acc[i][2] + q4.z, acc[i][3] + q4.w);
        }
    } else {
        float* outp = g_Qu + b * M_ * NT_;
#pragma unroll
        for (int i = 0; i < 4; i++) {
            int r = ty * 4 + i, cc = jb + tx * 4;
            float4 q4 = *(const float4*)(Qb + (size_t)(128 + r) * NT_ + cc);
            *(float4*)(outp + r * NT_ + cc) =
                make_float4(acc[i][0] + q4.x, acc[i][1] + q4.y, acc[i][2] + q4.z, acc[i][3] + q4.w);
        }
    }
}

// ---------------- k3: Cholesky(Quu) + 129-RHS solve -> K, k, vn ----------------
// sL rows padded to 68 floats (272B, 16B-aligned) for float4 reads.
// sLT = L^T so the backward solve also reads contiguous rows.
__global__ __launch_bounds__(256) void k3_solve(int t) {
    int b = blockIdx.x, tid = threadIdx.x;
    __shared__ __align__(16) float sL[64 * 68];
    __shared__ __align__(16) float sLT[64 * 68];
    __shared__ float sInvD[64];
    __shared__ float sk[64];
    const float* Qub = g_Qu + b * M_ * NT_;

    for (int idx = tid; idx < 64 * 64; idx += 256) {
        int i = idx >> 6, j = idx & 63;
        sL[i * 68 + j] = Qub[i * NT_ + 128 + j];
    }
    __syncthreads();

    // lower Cholesky in place; diag kept as reciprocal sqrt in sInvD
    for (int i = 0; i < 64; i++) {
        float dinv = rsqrtf(sL[i * 68 + i]);
        if (tid < 64) {
            if (tid == i) sInvD[i] = dinv;
            else if (tid > i) sL[tid * 68 + i] *= dinv;
        }
        __syncthreads();
#pragma unroll
        for (int q = 0; q < 16; q++) {
            int idx = q * 256 + tid;
            int j = idx >> 6, cc = idx & 63;
            if (cc > i && cc <= j)
                sL[j * 68 + cc] -= sL[j * 68 + i] * sL[cc * 68 + i];
        }
        __syncthreads();
    }

    // transpose lower triangle into sLT (sLT[j][i] = L[i][j], i > j)
    for (int idx = tid; idx < 64 * 64; idx += 256) {
        int i = idx >> 6, j = idx & 63;
        if (i > j) sLT[j * 68 + i] = sL[i * 68 + j];
    }
    __syncthreads();

    // one lane per RHS column: cols 0..127 = Qux, col 128 = qu.
    // Fully unrolled so y[] stays in registers; float4 L reads.
    int c = tid;
    if (c < 129) {
        float y[64];
        const float* rhsp = (c < 128) ? (Qub + c) : (g_qhat + b * NT_ + 128);
        int rstride = (c < 128) ? NT_ : 1;
#pragma unroll
        for (int j = 0; j < 64; j++) {
            float s = 0.f;
            const float4* Lr = (const float4*)&sL[j * 68];
#pragma unroll
            for (int i4 = 0; i4 < (j >> 2); i4++) {
                float4 l4 = Lr[i4];
                s += l4.x * y[4 * i4] + l4.y * y[4 * i4 + 1]
                   + l4.z * y[4 * i4 + 2] + l4.w * y[4 * i4 + 3];
            }
#pragma unroll
            for (int i = (j >> 2) << 2; i < j; i++) s += sL[j * 68 + i] * y[i];
            y[j] = (rhsp[j * rstride] - s) * sInvD[j];
        }
#pragma unroll
        for (int j = 63; j >= 0; j--) {
            float s = 0.f;
            int i = j + 1;
#pragma unroll
            for (; (i & 3) && i < 64; i++) s += sLT[j * 68 + i] * y[i];
            const float4* Ur = (const float4*)&sLT[j * 68];
#pragma unroll
            for (int i4 = (i >> 2); i4 < 16; i4++) {
                float4 u4 = Ur[i4];
                s += u4.x * y[4 * i4] + u4.y * y[4 * i4 + 1]
                   + u4.z * y[4 * i4 + 2] + u4.w * y[4 * i4 + 3];
            }
            y[j] = (y[j] - s) * sInvD[j];
        }
        if (c < 128) {
            float* Kb = g_K + ((size_t)t * B_ + b) * (M_ * N_);
#pragma unroll
            for (int j = 0; j < 64; j++) Kb[j * 128 + c] = -y[j];
        } else {
            float* kb = g_k + ((size_t)t * B_ + b) * M_;
#pragma unroll
            for (int j = 0; j < 64; j++) { kb[j] = -y[j]; sk[j] = -y[j]; }
        }
    }
    __syncthreads();

    // vn = qx + Qux^T k
    if (tid < 128) {
        float acc = g_qhat[b * NT_ + tid];
#pragma unroll 8
        for (int m = 0; m < 64; m++) acc += Qub[m * NT_ + tid] * sk[m];
        g_v[b * 128 + tid] = acc;
    }
}

// ---------------- k4: Vn = Qxx + Qux^T @ K ----------------
__global__ __launch_bounds__(256) void k4_Vn(int t) {
    int b = blockIdx.y, bx = blockIdx.x, tid = threadIdx.x;
    int ib = (bx >> 1) * 64, jb = (bx & 1) * 64;
    const float* Qub = g_Qu + b * M_ * NT_;
    const float* Kb = g_K + ((size_t)t * B_ + b) * (M_ * N_);
    __shared__ float As[16][64];
    __shared__ float Bs[16][64];
    int tx = tid & 15, ty = tid >> 4;
    float acc[4][4] = {};

    for (int kb = 0; kb < 4; kb++) {
        int k = kb * 16 + ty;
        *(float4*)&As[ty][tx * 4] = *(const float4*)(Qub + k * NT_ + ib + tx * 4);
        *(float4*)&Bs[ty][tx * 4] = *(const float4*)(Kb + k * 128 + jb + tx * 4);
        __syncthreads();
#pragma unroll
        for (int kk = 0; kk < 16; kk++) {
            float4 a = *(float4*)&As[kk][ty * 4];
            float4 bq = *(float4*)&Bs[kk][tx * 4];
            FMA16(a, bq)
        }
        __syncthreads();
    }
    const float* Qxxb = g_Qxx + b * N_ * N_;
    float* Vb = g_V + b * N_ * N_;
#pragma unroll
    for (int i = 0; i < 4; i++) {
        int r = ib + ty * 4 + i, cc = jb + tx * 4;
        float4 q4 = *(const float4*)(Qxxb + r * N_ + cc);
        *(float4*)(Vb + r * N_ + cc) =
            make_float4(acc[i][0] + q4.x, acc[i][1] + q4.y, acc[i][2] + q4.z, acc[i][3] + q4.w);
    }
}

// ---------------- forward rollout ----------------
__global__ __launch_bounds__(256) void kfwd(const float* __restrict__ A,
                                            const float* __restrict__ Bm,
                                            const float* __restrict__ c1,
                                            const float* __restrict__ xinit,
                                            float* __restrict__ out) {
    int b = blockIdx.x, tid = threadIdx.x;
    int warp = tid >> 5, lane = tid & 31;
    __shared__ float sx[128], su[64], sxn[128];
    if (tid < 128) sx[tid] = xinit[b * 128 + tid];
    __syncthreads();

    for (int t = 0; t < 128; t++) {
        size_t bt = (size_t)b * T_ + t;
        const float* Kb = g_K + ((size_t)t * B_ + b) * (M_ * N_);
        const float* kb = g_k + ((size_t)t * B_ + b) * M_;
        for (int r = warp; r < 64; r += 8) {
            const float* kr = Kb + r * 128;
            float s = kr[lane] * sx[lane] + kr[32 + lane] * sx[32 + lane]
                    + kr[64 + lane] * sx[64 + lane] + kr[96 + lane] * sx[96 + lane];
#pragma unroll
            for (int o = 16; o; o >>= 1) s += __shfl_down_sync(0xffffffffu, s, o);
            if (lane == 0) su[r] = s + kb[r];
        }
        if (tid < 128) out[bt * NT_ + tid] = sx[tid];
        __syncthreads();
        if (tid < 64) out[bt * NT_ + 128 + tid] = su[tid];

        const float* Ab = A + bt * (size_t)(N_ * N_);
        const float* Bb = Bm + bt * (size_t)(N_ * M_);
        for (int r = warp; r < 128; r += 8) {
            const float* ar = Ab + r * 128;
            const float* br = Bb + r * 64;
            float s = ar[lane] * sx[lane] + ar[32 + lane] * sx[32 + lane]
                    + ar[64 + lane] * sx[64 + lane] + ar[96 + lane] * sx[96 + lane]
                    + br[lane] * su[lane] + br[32 + lane] * su[32 + lane];
#pragma unroll
            for (int o = 16; o; o >>= 1) s += __shfl_down_sync(0xffffffffu, s, o);
            if (lane == 0) sxn[r] = s + c1[bt * 128 + r];
        }
        __syncthreads();
        if (tid < 128) sx[tid] = sxn[tid];
        __syncthreads();
    }
}

// ---------------- launch ----------------
extern "C" void kernel_launch(void* const* d_in, const int* in_sizes, int n_in,
                              void* d_out, int out_size) {
    const float *A = 0, *Bm = 0, *c1 = 0, *Q = 0, *p = 0, *xinit = 0;
    for (int i = 0; i < n_in; i++) {
        switch (in_sizes[i]) {
            case 67108864:  A = (const float*)d_in[i]; break;      // 32*128*128*128
            case 33554432:  Bm = (const float*)d_in[i]; break;     // 32*128*128*64
            case 524288:    c1 = (const float*)d_in[i]; break;     // 32*128*128
            case 150994944: Q = (const float*)d_in[i]; break;      // 32*128*192*192
            case 786432:    p = (const float*)d_in[i]; break;      // 32*128*192
            case 4096:      xinit = (const float*)d_in[i]; break;  // 32*128
        }
    }
    float* out = (float*)d_out;

    kzero<<<(B_ * N_ * N_ + 255) / 256, 256>>>();
    for (int t = T_ - 1; t >= 0; t--) {
        k1_VF<<<dim3(7, B_), 256>>>(A, Bm, c1, t);
        k2_Qhat<<<dim3(8, B_), 256>>>(A, Bm, Q, p, t);
        k3_solve<<<B_, 256>>>(t);
        k4_Vn<<<dim3(4, B_), 256>>>(t);
    }
    kfwd<<<B_, 256>>>(A, Bm, c1, xinit, out);
}

// round 5
// speedup vs baseline: 1.5903x; 1.0701x over previous
#include <cuda_runtime.h>

#define B_ 32
#define T_ 128
#define N_ 128
#define M_ 64
#define NT_ 192

// ---------------- device scratch (no allocations allowed) ----------------
__device__ float g_V[B_ * N_ * N_];
__device__ float g_v[B_ * N_];
__device__ float g_w[B_ * N_];
__device__ float g_VF[B_ * N_ * NT_];
__device__ float g_Qxx[B_ * N_ * N_];
__device__ float g_Qu[B_ * M_ * NT_];   // rows 0..63: cols 0..127 = Qux, 128..191 = Quu
__device__ float g_qhat[B_ * NT_];
__device__ float g_K[(size_t)T_ * B_ * M_ * N_];
__device__ float g_k[T_ * B_ * M_];

#define FMA16(a, bq)                                                                   \
    acc[0][0] += a.x * bq.x; acc[0][1] += a.x * bq.y; acc[0][2] += a.x * bq.z; acc[0][3] += a.x * bq.w; \
    acc[1][0] += a.y * bq.x; acc[1][1] += a.y * bq.y; acc[1][2] += a.y * bq.z; acc[1][3] += a.y * bq.w; \
    acc[2][0] += a.z * bq.x; acc[2][1] += a.z * bq.y; acc[2][2] += a.z * bq.z; acc[2][3] += a.z * bq.w; \
    acc[3][0] += a.w * bq.x; acc[3][1] += a.w * bq.y; acc[3][2] += a.w * bq.z; acc[3][3] += a.w * bq.w;

// ---------------- init ----------------
__global__ void kzero() {
    int idx = blockIdx.x * 256 + threadIdx.x;
    if (idx < B_ * N_ * N_) g_V[idx] = 0.0f;
    if (idx < B_ * N_) g_v[idx] = 0.0f;
}

// ---------------- k1: VF = V @ [A|B]  (uses V symmetry), w = V c + v ----------------
__global__ __launch_bounds__(256) void k1_VF(const float* __restrict__ A,
                                             const float* __restrict__ Bm,
                                             const float* __restrict__ c1, int t) {
    int b = blockIdx.y;
    int bx = blockIdx.x;
    int tid = threadIdx.x;
    const float* Vb = g_V + b * N_ * N_;
    size_t bt = (size_t)b * T_ + t;

    if (bx == 6) {  // w = V c + v  (V symmetric -> coalesced column read)
        __shared__ float cs[128];
        if (tid < 128) cs[tid] = c1[bt * 128 + tid];
        __syncthreads();
        if (tid < 128) {
            float acc = g_v[b * 128 + tid];
#pragma unroll 8
            for (int m = 0; m < 128; m++) acc += Vb[m * 128 + tid] * cs[m];
            g_w[b * 128 + tid] = acc;
        }
        return;
    }

    int tr = bx / 3, tc = bx % 3;
    int rb = tr * 64, cb = tc * 64;
    const float* Fsrc; int ldF, coff;
    if (cb < 128) { Fsrc = A + bt * (size_t)(N_ * N_); ldF = 128; coff = cb; }
    else          { Fsrc = Bm + bt * (size_t)(N_ * M_); ldF = 64;  coff = 0;  }

    __shared__ float As[16][64];
    __shared__ float Bs[16][64];
    int tx = tid & 15, ty = tid >> 4;
    float acc[4][4] = {};

    for (int kb = 0; kb < 8; kb++) {
        int k = kb * 16 + ty;
        // V symmetric: V[row][k] == V[k][row]
        *(float4*)&As[ty][tx * 4] = *(const float4*)(Vb + k * 128 + rb + tx * 4);
        *(float4*)&Bs[ty][tx * 4] = *(const float4*)(Fsrc + (size_t)k * ldF + coff + tx * 4);
        __syncthreads();
#pragma unroll
        for (int kk = 0; kk < 16; kk++) {
            float4 a = *(float4*)&As[kk][ty * 4];
            float4 bq = *(float4*)&Bs[kk][tx * 4];
            FMA16(a, bq)
        }
        __syncthreads();
    }
    float* outp = g_VF + b * N_ * NT_;
#pragma unroll
    for (int i = 0; i < 4; i++) {
        *(float4*)(outp + (rb + ty * 4 + i) * NT_ + cb + tx * 4) =
            make_float4(acc[i][0], acc[i][1], acc[i][2], acc[i][3]);
    }
}

// ---------------- k2: Qxx = Qxx + A^T VF ; [Qux|Quu] = Q_u + B^T VF ; qhat ----------------
__global__ __launch_bounds__(256) void k2_Qhat(const float* __restrict__ A,
                                               const float* __restrict__ Bm,
                                               const float* __restrict__ Q,
                                               const float* __restrict__ p, int t) {
    int b = blockIdx.y, bx = blockIdx.x, tid = threadIdx.x;
    size_t bt = (size_t)b * T_ + t;

    if (bx == 7) {  // qhat = p + F^T w
        __shared__ float ws[128];
        if (tid < 128) ws[tid] = g_w[b * 128 + tid];
        __syncthreads();
        if (tid < 192) {
            float acc = p[bt * NT_ + tid];
            if (tid < 128) {
                const float* Ab = A + bt * (size_t)(N_ * N_);
#pragma unroll 4
                for (int n = 0; n < 128; n++) acc += Ab[n * 128 + tid] * ws[n];
            } else {
                const float* Bb = Bm + bt * (size_t)(N_ * M_);
                int j = tid - 128;
#pragma unroll 4
                for (int n = 0; n < 128; n++) acc += Bb[n * 64 + j] * ws[n];
            }
            g_qhat[b * NT_ + tid] = acc;
        }
        return;
    }

    bool isQxx = bx < 4;
    int ib, jb; const float* Asrc; int lda, aoff;
    if (isQxx) { ib = (bx >> 1) * 64; jb = (bx & 1) * 64; Asrc = A + bt * (size_t)(N_ * N_); lda = 128; aoff = ib; }
    else       { ib = 0; jb = (bx - 4) * 64; Asrc = Bm + bt * (size_t)(N_ * M_); lda = 64; aoff = 0; }

    __shared__ float As[16][64];
    __shared__ float Bs[16][64];
    int tx = tid & 15, ty = tid >> 4;
    const float* VFb = g_VF + b * N_ * NT_;
    float acc[4][4] = {};

    for (int kb = 0; kb < 8; kb++) {
        int k = kb * 16 + ty;
        *(float4*)&As[ty][tx * 4] = *(const float4*)(Asrc + (size_t)k * lda + aoff + tx * 4);
        *(float4*)&Bs[ty][tx * 4] = *(const float4*)(VFb + k * NT_ + jb + tx * 4);
        __syncthreads();
#pragma unroll
        for (int kk = 0; kk < 16; kk++) {
            float4 a = *(float4*)&As[kk][ty * 4];
            float4 bq = *(float4*)&Bs[kk][tx * 4];
            FMA16(a, bq)
        }
        __syncthreads();
    }

    const float* Qb = Q + bt * (size_t)(NT_ * NT_);
    if (isQxx) {
        float* outp = g_Qxx + b * N_ * N_;
#pragma unroll
        for (int i = 0; i < 4; i++) {
            int r = ib + ty * 4 + i, cc = jb + tx * 4;
            float4 q4 = *(const float4*)(Qb + (size_t)r * NT_ + cc);
            *(float4*)(outp + r * N_ + cc) =
                make_float4(acc[i][0] + q4.x, acc[i][1] + q4.y, acc[i][2] + q4.z, acc[i][3] + q4.w);
        }
    } else {
        float* outp = g_Qu + b * M_ * NT_;
#pragma unroll
        for (int i = 0; i < 4; i++) {
            int r = ty * 4 + i, cc = jb + tx * 4;
            float4 q4 = *(const float4*)(Qb + (size_t)(128 + r) * NT_ + cc);
            *(float4*)(outp + r * NT_ + cc) =
                make_float4(acc[i][0] + q4.x, acc[i][1] + q4.y, acc[i][2] + q4.z, acc[i][3] + q4.w);
        }
    }
}

// ---------------- k3: blocked Cholesky(Quu) + 129-RHS solve -> K, k, vn ----------------
// sL rows padded to 68 floats (16B-aligned rows for float4).
// sPT = transposed current panel (conflict-free trailing update).
// sLT = L^T for the backward solve.
__global__ __launch_bounds__(256) void k3_solve(int t) {
    int b = blockIdx.x, tid = threadIdx.x;
    __shared__ __align__(16) float sL[64 * 68];
    __shared__ __align__(16) float sLT[64 * 68];
    __shared__ float sPT[16 * 66];
    __shared__ float sInvD[64];
    __shared__ float sk[64];
    const float* Qub = g_Qu + b * M_ * NT_;

    for (int idx = tid; idx < 64 * 64; idx += 256) {
        int i = idx >> 6, j = idx & 63;
        sL[i * 68 + j] = Qub[i * NT_ + 128 + j];
    }
    __syncthreads();

    // ---- blocked lower Cholesky, 16-wide panels ----
    for (int kb = 0; kb < 64; kb += 16) {
        // 1) factor 16x16 diagonal block (warp 0 only, lanes 0..15 = rows)
        if (tid < 32) {
            int l = tid;
#pragma unroll
            for (int i = 0; i < 16; i++) {
                int ci = kb + i;
                float dinv = rsqrtf(sL[ci * 68 + ci]);
                if (l == 0) sInvD[ci] = dinv;
                __syncwarp();
                if (l > i && l < 16) sL[(kb + l) * 68 + ci] *= dinv;
                __syncwarp();
                if (l > i && l < 16) {
                    float lv = sL[(kb + l) * 68 + ci];
                    for (int c = i + 1; c <= l; c++)
                        sL[(kb + l) * 68 + kb + c] -= lv * sL[(kb + c) * 68 + ci];
                }
                __syncwarp();
            }
        }
        __syncthreads();

        int rem = 48 - kb;  // panel rows below the diagonal block
        if (rem > 0) {
            // 2) panel solve: one thread per row r = kb+16..63
            if (tid < rem) {
                int r = kb + 16 + tid;
                float a[16];
#pragma unroll
                for (int i = 0; i < 16; i++) a[i] = sL[r * 68 + kb + i];
#pragma unroll
                for (int i = 0; i < 16; i++) {
                    float s = a[i];
#pragma unroll
                    for (int m = 0; m < i; m++) s -= a[m] * sL[(kb + i) * 68 + kb + m];
                    a[i] = s * sInvD[kb + i];
                }
#pragma unroll
                for (int i = 0; i < 16; i++) {
                    sL[r * 68 + kb + i] = a[i];
                    sPT[i * 66 + r] = a[i];   // transposed copy for the update
                }
            }
            __syncthreads();

            // 3) trailing rank-16 update (reads via sPT: conflict-free)
            int total = rem * 64;
            for (int idx = tid; idx < total; idx += 256) {
                int jr = kb + 16 + (idx >> 6);
                int c = idx & 63;
                if (c >= kb + 16 && c <= jr) {
                    float s = sL[jr * 68 + c];
#pragma unroll
                    for (int m = 0; m < 16; m++)
                        s -= sPT[m * 66 + jr] * sPT[m * 66 + c];
                    sL[jr * 68 + c] = s;
                }
            }
            __syncthreads();
        }
    }

    // transpose lower triangle into sLT (sLT[j][i] = L[i][j], i > j)
    for (int idx = tid; idx < 64 * 64; idx += 256) {
        int i = idx >> 6, j = idx & 63;
        if (i > j) sLT[j * 68 + i] = sL[i * 68 + j];
    }
    __syncthreads();

    // ---- one lane per RHS column: cols 0..127 = Qux, col 128 = qu ----
    // Fully unrolled, y[] in registers, 4 independent accumulators.
    int c = tid;
    if (c < 129) {
        float y[64];
        const float* rhsp = (c < 128) ? (Qub + c) : (g_qhat + b * NT_ + 128);
        int rstride = (c < 128) ? NT_ : 1;
#pragma unroll
        for (int j = 0; j < 64; j++) {
            const float4* Lr = (const float4*)&sL[j * 68];
            float s0 = 0.f, s1 = 0.f, s2 = 0.f, s3 = 0.f;
#pragma unroll
            for (int i4 = 0; i4 < (j >> 2); i4++) {
                float4 l4 = Lr[i4];
                s0 += l4.x * y[4 * i4];
                s1 += l4.y * y[4 * i4 + 1];
                s2 += l4.z * y[4 * i4 + 2];
                s3 += l4.w * y[4 * i4 + 3];
            }
            float s = (s0 + s1) + (s2 + s3);
#pragma unroll
            for (int i = (j & ~3); i < j; i++) s += sL[j * 68 + i] * y[i];
            y[j] = (rhsp[j * rstride] - s) * sInvD[j];
        }
#pragma unroll
        for (int j = 63; j >= 0; j--) {
            int ibeg = j + 1;
            int i4beg = (ibeg + 3) >> 2;
            float s = 0.f;
#pragma unroll
            for (int i = ibeg; i < (i4beg << 2) && i < 64; i++) s += sLT[j * 68 + i] * y[i];
            const float4* Ur = (const float4*)&sLT[j * 68];
            float s0 = 0.f, s1 = 0.f, s2 = 0.f, s3 = 0.f;
#pragma unroll
            for (int i4 = i4beg; i4 < 16; i4++) {
                float4 u4 = Ur[i4];
                s0 += u4.x * y[4 * i4];
                s1 += u4.y * y[4 * i4 + 1];
                s2 += u4.z * y[4 * i4 + 2];
                s3 += u4.w * y[4 * i4 + 3];
            }
            y[j] = (y[j] - s - ((s0 + s1) + (s2 + s3))) * sInvD[j];
        }
        if (c < 128) {
            float* Kb = g_K + ((size_t)t * B_ + b) * (M_ * N_);
#pragma unroll
            for (int j = 0; j < 64; j++) Kb[j * 128 + c] = -y[j];
        } else {
            float* kb = g_k + ((size_t)t * B_ + b) * M_;
#pragma unroll
            for (int j = 0; j < 64; j++) { kb[j] = -y[j]; sk[j] = -y[j]; }
        }
    }
    __syncthreads();

    // vn = qx + Qux^T k
    if (tid < 128) {
        float acc = g_qhat[b * NT_ + tid];
#pragma unroll 8
        for (int m = 0; m < 64; m++) acc += Qub[m * NT_ + tid] * sk[m];
        g_v[b * 128 + tid] = acc;
    }
}

// ---------------- k4: Vn = Qxx + Qux^T @ K ----------------
__global__ __launch_bounds__(256) void k4_Vn(int t) {
    int b = blockIdx.y, bx = blockIdx.x, tid = threadIdx.x;
    int ib = (bx >> 1) * 64, jb = (bx & 1) * 64;
    const float* Qub = g_Qu + b * M_ * NT_;
    const float* Kb = g_K + ((size_t)t * B_ + b) * (M_ * N_);
    __shared__ float As[16][64];
    __shared__ float Bs[16][64];
    int tx = tid & 15, ty = tid >> 4;
    float acc[4][4] = {};

    for (int kb = 0; kb < 4; kb++) {
        int k = kb * 16 + ty;
        *(float4*)&As[ty][tx * 4] = *(const float4*)(Qub + k * NT_ + ib + tx * 4);
        *(float4*)&Bs[ty][tx * 4] = *(const float4*)(Kb + k * 128 + jb + tx * 4);
        __syncthreads();
#pragma unroll
        for (int kk = 0; kk < 16; kk++) {
            float4 a = *(float4*)&As[kk][ty * 4];
            float4 bq = *(float4*)&Bs[kk][tx * 4];
            FMA16(a, bq)
        }
        __syncthreads();
    }
    const float* Qxxb = g_Qxx + b * N_ * N_;
    float* Vb = g_V + b * N_ * N_;
#pragma unroll
    for (int i = 0; i < 4; i++) {
        int r = ib + ty * 4 + i, cc = jb + tx * 4;
        float4 q4 = *(const float4*)(Qxxb + r * N_ + cc);
        *(float4*)(Vb + r * N_ + cc) =
            make_float4(acc[i][0] + q4.x, acc[i][1] + q4.y, acc[i][2] + q4.z, acc[i][3] + q4.w);
    }
}

// ---------------- forward rollout ----------------
__global__ __launch_bounds__(256) void kfwd(const float* __restrict__ A,
                                            const float* __restrict__ Bm,
                                            const float* __restrict__ c1,
                                            const float* __restrict__ xinit,
                                            float* __restrict__ out) {
    int b = blockIdx.x, tid = threadIdx.x;
    int warp = tid >> 5, lane = tid & 31;
    __shared__ float sx[128], su[64], sxn[128];
    if (tid < 128) sx[tid] = xinit[b * 128 + tid];
    __syncthreads();

    for (int t = 0; t < 128; t++) {
        size_t bt = (size_t)b * T_ + t;
        const float* Kb = g_K + ((size_t)t * B_ + b) * (M_ * N_);
        const float* kb = g_k + ((size_t)t * B_ + b) * M_;
        for (int r = warp; r < 64; r += 8) {
            const float* kr = Kb + r * 128;
            float s = kr[lane] * sx[lane] + kr[32 + lane] * sx[32 + lane]
                    + kr[64 + lane] * sx[64 + lane] + kr[96 + lane] * sx[96 + lane];
#pragma unroll
            for (int o = 16; o; o >>= 1) s += __shfl_down_sync(0xffffffffu, s, o);
            if (lane == 0) su[r] = s + kb[r];
        }
        if (tid < 128) out[bt * NT_ + tid] = sx[tid];
        __syncthreads();
        if (tid < 64) out[bt * NT_ + 128 + tid] = su[tid];

        const float* Ab = A + bt * (size_t)(N_ * N_);
        const float* Bb = Bm + bt * (size_t)(N_ * M_);
        for (int r = warp; r < 128; r += 8) {
            const float* ar = Ab + r * 128;
            const float* br = Bb + r * 64;
            float s = ar[lane] * sx[lane] + ar[32 + lane] * sx[32 + lane]
                    + ar[64 + lane] * sx[64 + lane] + ar[96 + lane] * sx[96 + lane]
                    + br[lane] * su[lane] + br[32 + lane] * su[32 + lane];
#pragma unroll
            for (int o = 16; o; o >>= 1) s += __shfl_down_sync(0xffffffffu, s, o);
            if (lane == 0) sxn[r] = s + c1[bt * 128 + r];
        }
        __syncthreads();
        if (tid < 128) sx[tid] = sxn[tid];
        __syncthreads();
    }
}

// ---------------- launch ----------------
extern "C" void kernel_launch(void* const* d_in, const int* in_sizes, int n_in,
                              void* d_out, int out_size) {
    const float *A = 0, *Bm = 0, *c1 = 0, *Q = 0, *p = 0, *xinit = 0;
    for (int i = 0; i < n_in; i++) {
        switch (in_sizes[i]) {
            case 67108864:  A = (const float*)d_in[i]; break;      // 32*128*128*128
            case 33554432:  Bm = (const float*)d_in[i]; break;     // 32*128*128*64
            case 524288:    c1 = (const float*)d_in[i]; break;     // 32*128*128
            case 150994944: Q = (const float*)d_in[i]; break;      // 32*128*192*192
            case 786432:    p = (const float*)d_in[i]; break;      // 32*128*192
            case 4096:      xinit = (const float*)d_in[i]; break;  // 32*128
        }
    }
    float* out = (float*)d_out;

    kzero<<<(B_ * N_ * N_ + 255) / 256, 256>>>();
    for (int t = T_ - 1; t >= 0; t--) {
        k1_VF<<<dim3(7, B_), 256>>>(A, Bm, c1, t);
        k2_Qhat<<<dim3(8, B_), 256>>>(A, Bm, Q, p, t);
        k3_solve<<<B_, 256>>>(t);
        k4_Vn<<<dim3(4, B_), 256>>>(t);
    }
    kfwd<<<B_, 256>>>(A, Bm, c1, xinit, out);
}

// round 6
// speedup vs baseline: 1.8984x; 1.1937x over previous
#include <cuda_runtime.h>

#define B_ 32
#define T_ 128
#define N_ 128
#define M_ 64
#define NT_ 192

// ---------------- device scratch (no allocations allowed) ----------------
__device__ float g_V[B_ * N_ * N_];
__device__ float g_v[B_ * N_];
__device__ float g_w[B_ * N_];
__device__ float g_VF[B_ * N_ * NT_];
__device__ float g_Qxx[B_ * N_ * N_];
__device__ float g_Qu[B_ * M_ * NT_];   // rows 0..63: cols 0..127 = Qux, 128..191 = Quu
__device__ float g_qhat[B_ * NT_];
__device__ float g_K[(size_t)T_ * B_ * M_ * N_];
__device__ float g_k[T_ * B_ * M_];

#define FMA16(a, bq)                                                                   \
    acc[0][0] += a.x * bq.x; acc[0][1] += a.x * bq.y; acc[0][2] += a.x * bq.z; acc[0][3] += a.x * bq.w; \
    acc[1][0] += a.y * bq.x; acc[1][1] += a.y * bq.y; acc[1][2] += a.y * bq.z; acc[1][3] += a.y * bq.w; \
    acc[2][0] += a.z * bq.x; acc[2][1] += a.z * bq.y; acc[2][2] += a.z * bq.z; acc[2][3] += a.z * bq.w; \
    acc[3][0] += a.w * bq.x; acc[3][1] += a.w * bq.y; acc[3][2] += a.w * bq.z; acc[3][3] += a.w * bq.w;

// ---------------- init ----------------
__global__ void kzero() {
    int idx = blockIdx.x * 256 + threadIdx.x;
    if (idx < B_ * N_ * N_) g_V[idx] = 0.0f;
    if (idx < B_ * N_) g_v[idx] = 0.0f;
}

// ---------------- k1: VF = V @ [A|B]  (uses V symmetry), w = V c + v ----------------
__global__ __launch_bounds__(256) void k1_VF(const float* __restrict__ A,
                                             const float* __restrict__ Bm,
                                             const float* __restrict__ c1, int t) {
    int b = blockIdx.y;
    int bx = blockIdx.x;
    int tid = threadIdx.x;
    const float* Vb = g_V + b * N_ * N_;
    size_t bt = (size_t)b * T_ + t;

    if (bx == 6) {  // w = V c + v  (V symmetric -> coalesced column read)
        __shared__ float cs[128];
        if (tid < 128) cs[tid] = c1[bt * 128 + tid];
        __syncthreads();
        if (tid < 128) {
            float acc = g_v[b * 128 + tid];
#pragma unroll 8
            for (int m = 0; m < 128; m++) acc += Vb[m * 128 + tid] * cs[m];
            g_w[b * 128 + tid] = acc;
        }
        return;
    }

    int tr = bx / 3, tc = bx % 3;
    int rb = tr * 64, cb = tc * 64;
    const float* Fsrc; int ldF, coff;
    if (cb < 128) { Fsrc = A + bt * (size_t)(N_ * N_); ldF = 128; coff = cb; }
    else          { Fsrc = Bm + bt * (size_t)(N_ * M_); ldF = 64;  coff = 0;  }

    __shared__ float As[16][64];
    __shared__ float Bs[16][64];
    int tx = tid & 15, ty = tid >> 4;
    float acc[4][4] = {};

    for (int kb = 0; kb < 8; kb++) {
        int k = kb * 16 + ty;
        // V symmetric: V[row][k] == V[k][row]
        *(float4*)&As[ty][tx * 4] = *(const float4*)(Vb + k * 128 + rb + tx * 4);
        *(float4*)&Bs[ty][tx * 4] = *(const float4*)(Fsrc + (size_t)k * ldF + coff + tx * 4);
        __syncthreads();
#pragma unroll
        for (int kk = 0; kk < 16; kk++) {
            float4 a = *(float4*)&As[kk][ty * 4];
            float4 bq = *(float4*)&Bs[kk][tx * 4];
            FMA16(a, bq)
        }
        __syncthreads();
    }
    float* outp = g_VF + b * N_ * NT_;
#pragma unroll
    for (int i = 0; i < 4; i++) {
        *(float4*)(outp + (rb + ty * 4 + i) * NT_ + cb + tx * 4) =
            make_float4(acc[i][0], acc[i][1], acc[i][2], acc[i][3]);
    }
}

// ---------------- k2: Qxx = Qxx + A^T VF ; [Qux|Quu] = Q_u + B^T VF ; qhat ----------------
__global__ __launch_bounds__(256) void k2_Qhat(const float* __restrict__ A,
                                               const float* __restrict__ Bm,
                                               const float* __restrict__ Q,
                                               const float* __restrict__ p, int t) {
    int b = blockIdx.y, bx = blockIdx.x, tid = threadIdx.x;
    size_t bt = (size_t)b * T_ + t;

    if (bx == 7) {  // qhat = p + F^T w
        __shared__ float ws[128];
        if (tid < 128) ws[tid] = g_w[b * 128 + tid];
        __syncthreads();
        if (tid < 192) {
            float acc = p[bt * NT_ + tid];
            if (tid < 128) {
                const float* Ab = A + bt * (size_t)(N_ * N_);
#pragma unroll 4
                for (int n = 0; n < 128; n++) acc += Ab[n * 128 + tid] * ws[n];
            } else {
                const float* Bb = Bm + bt * (size_t)(N_ * M_);
                int j = tid - 128;
#pragma unroll 4
                for (int n = 0; n < 128; n++) acc += Bb[n * 64 + j] * ws[n];
            }
            g_qhat[b * NT_ + tid] = acc;
        }
        return;
    }

    bool isQxx = bx < 4;
    int ib, jb; const float* Asrc; int lda, aoff;
    if (isQxx) { ib = (bx >> 1) * 64; jb = (bx & 1) * 64; Asrc = A + bt * (size_t)(N_ * N_); lda = 128; aoff = ib; }
    else       { ib = 0; jb = (bx - 4) * 64; Asrc = Bm + bt * (size_t)(N_ * M_); lda = 64; aoff = 0; }

    __shared__ float As[16][64];
    __shared__ float Bs[16][64];
    int tx = tid & 15, ty = tid >> 4;
    const float* VFb = g_VF + b * N_ * NT_;
    float acc[4][4] = {};

    for (int kb = 0; kb < 8; kb++) {
        int k = kb * 16 + ty;
        *(float4*)&As[ty][tx * 4] = *(const float4*)(Asrc + (size_t)k * lda + aoff + tx * 4);
        *(float4*)&Bs[ty][tx * 4] = *(const float4*)(VFb + k * NT_ + jb + tx * 4);
        __syncthreads();
#pragma unroll
        for (int kk = 0; kk < 16; kk++) {
            float4 a = *(float4*)&As[kk][ty * 4];
            float4 bq = *(float4*)&Bs[kk][tx * 4];
            FMA16(a, bq)
        }
        __syncthreads();
    }

    const float* Qb = Q + bt * (size_t)(NT_ * NT_);
    if (isQxx) {
        float* outp = g_Qxx + b * N_ * N_;
#pragma unroll
        for (int i = 0; i < 4; i++) {
            int r = ib + ty * 4 + i, cc = jb + tx * 4;
            float4 q4 = *(const float4*)(Qb + (size_t)r * NT_ + cc);
            *(float4*)(outp + r * N_ + cc) =
                make_float4(acc[i][0] + q4.x, acc[i][1] + q4.y, acc[i][2] + q4.z, acc[i][3] + q4.w);
        }
    } else {
        float* outp = g_Qu + b * M_ * NT_;
#pragma unroll
        for (int i = 0; i < 4; i++) {
            int r = ty * 4 + i, cc = jb + tx * 4;
            float4 q4 = *(const float4*)(Qb + (size_t)(128 + r) * NT_ + cc);
            *(float4*)(outp + r * NT_ + cc) =
                make_float4(acc[i][0] + q4.x, acc[i][1] + q4.y, acc[i][2] + q4.z, acc[i][3] + q4.w);
        }
    }
}

// ---------------- k3: blocked Cholesky(Quu) + 129-RHS solve -> K, k, vn ----------------
// Dynamic smem layout:
//   sL   [64*68]  : L in lower triangle; after mirror pass, L^T in strict upper.
//   sR   [64*132] : staged RHS (cols 0..127 = Qux, col 128 = qu)
//   sPT  [16*66]  : transposed panel for trailing update
//   sInvD[64], sk[64]
#define SM_L   0
#define SM_R   (64 * 68)
#define SM_PT  (SM_R + 64 * 132)
#define SM_ID  (SM_PT + 16 * 66)
#define SM_K   (SM_ID + 64)
#define SM_TOT (SM_K + 64)   // floats

__global__ __launch_bounds__(256) void k3_solve(int t) {
    extern __shared__ __align__(16) float sm[];
    float* sL = sm + SM_L;
    float* sR = sm + SM_R;
    float* sPT = sm + SM_PT;
    float* sInvD = sm + SM_ID;
    float* sk = sm + SM_K;

    int b = blockIdx.x, tid = threadIdx.x;
    const float* Qub = g_Qu + b * M_ * NT_;

    // stage Quu into sL and RHS into sR (coalesced, full CTA)
    for (int idx = tid; idx < 64 * 64; idx += 256) {
        int i = idx >> 6, j = idx & 63;
        sL[i * 68 + j] = Qub[i * NT_ + 128 + j];
    }
    for (int idx = tid; idx < 64 * 128; idx += 256) {
        int i = idx >> 7, c = idx & 127;
        sR[i * 132 + c] = Qub[i * NT_ + c];
    }
    if (tid < 64) sR[tid * 132 + 128] = g_qhat[b * NT_ + 128 + tid];
    __syncthreads();

    // ---- blocked lower Cholesky, 16-wide panels ----
    for (int kb = 0; kb < 64; kb += 16) {
        // 1) factor 16x16 diagonal block in registers via shfl (warp 0)
        if (tid < 32) {
            int l = tid & 15;
            int row = kb + l;
            float a[16];
#pragma unroll
            for (int i = 0; i < 16; i++) a[i] = sL[row * 68 + kb + i];
#pragma unroll
            for (int i = 0; i < 16; i++) {
                float aii = __shfl_sync(0xffffffffu, a[i], i);
                float dinv = rsqrtf(aii);
                a[i] *= dinv;
                if (tid == i) sInvD[kb + i] = dinv;
#pragma unroll
                for (int c = i + 1; c < 16; c++) {
                    float lci = __shfl_sync(0xffffffffu, a[i], c);
                    a[c] -= a[i] * lci;
                }
            }
            if (tid < 16) {
#pragma unroll
                for (int i = 0; i < 16; i++)
                    if (i <= l) sL[row * 68 + kb + i] = a[i];
            }
        }
        __syncthreads();

        int rem = 48 - kb;  // panel rows below the diagonal block
        if (rem > 0) {
            // 2) panel solve: one thread per row r = kb+16..63
            if (tid < rem) {
                int r = kb + 16 + tid;
                float a[16];
#pragma unroll
                for (int i = 0; i < 16; i++) a[i] = sL[r * 68 + kb + i];
#pragma unroll
                for (int i = 0; i < 16; i++) {
                    float s = a[i];
#pragma unroll
                    for (int m = 0; m < i; m++) s -= a[m] * sL[(kb + i) * 68 + kb + m];
                    a[i] = s * sInvD[kb + i];
                }
#pragma unroll
                for (int i = 0; i < 16; i++) {
                    sL[r * 68 + kb + i] = a[i];
                    sPT[i * 66 + r] = a[i];   // transposed copy for the update
                }
            }
            __syncthreads();

            // 3) trailing rank-16 update (reads via sPT: conflict-free)
            int total = rem * 64;
            for (int idx = tid; idx < total; idx += 256) {
                int jr = kb + 16 + (idx >> 6);
                int c = idx & 63;
                if (c >= kb + 16 && c <= jr) {
                    float s = sL[jr * 68 + c];
#pragma unroll
                    for (int m = 0; m < 16; m++)
                        s -= sPT[m * 66 + jr] * sPT[m * 66 + c];
                    sL[jr * 68 + c] = s;
                }
            }
            __syncthreads();
        }
    }

    // mirror strict lower triangle into strict upper: sL[j][i] = L[i][j] for j < i
    for (int idx = tid; idx < 64 * 64; idx += 256) {
        int i = idx >> 6, j = idx & 63;
        if (i > j) sL[j * 68 + i] = sL[i * 68 + j];
    }
    __syncthreads();

    // ---- one lane per RHS column (all operands in smem) ----
    int c = tid;
    if (c < 129) {
        float y[64];
#pragma unroll
        for (int j = 0; j < 64; j++) {
            const float4* Lr = (const float4*)&sL[j * 68];
            float s0 = 0.f, s1 = 0.f, s2 = 0.f, s3 = 0.f;
#pragma unroll
            for (int i4 = 0; i4 < (j >> 2); i4++) {
                float4 l4 = Lr[i4];
                s0 += l4.x * y[4 * i4];
                s1 += l4.y * y[4 * i4 + 1];
                s2 += l4.z * y[4 * i4 + 2];
                s3 += l4.w * y[4 * i4 + 3];
            }
            float s = (s0 + s1) + (s2 + s3);
#pragma unroll
            for (int i = (j & ~3); i < j; i++) s += sL[j * 68 + i] * y[i];
            y[j] = (sR[j * 132 + c] - s) * sInvD[j];
        }
#pragma unroll
        for (int j = 63; j >= 0; j--) {
            int ibeg = j + 1;
            int i4beg = (ibeg + 3) >> 2;
            float s = 0.f;
#pragma unroll
            for (int i = ibeg; i < (i4beg << 2) && i < 64; i++) s += sL[j * 68 + i] * y[i];
            const float4* Ur = (const float4*)&sL[j * 68];
            float s0 = 0.f, s1 = 0.f, s2 = 0.f, s3 = 0.f;
#pragma unroll
            for (int i4 = i4beg; i4 < 16; i4++) {
                float4 u4 = Ur[i4];
                s0 += u4.x * y[4 * i4];
                s1 += u4.y * y[4 * i4 + 1];
                s2 += u4.z * y[4 * i4 + 2];
                s3 += u4.w * y[4 * i4 + 3];
            }
            y[j] = (y[j] - s - ((s0 + s1) + (s2 + s3))) * sInvD[j];
        }
        if (c < 128) {
            float* Kb = g_K + ((size_t)t * B_ + b) * (M_ * N_);
#pragma unroll
            for (int j = 0; j < 64; j++) Kb[j * 128 + c] = -y[j];
        } else {
            float* kb = g_k + ((size_t)t * B_ + b) * M_;
#pragma unroll
            for (int j = 0; j < 64; j++) { kb[j] = -y[j]; sk[j] = -y[j]; }
        }
    }
    __syncthreads();

    // vn = qx + Qux^T k   (Qux read from staged sR: conflict-free rows)
    if (tid < 128) {
        float acc = g_qhat[b * NT_ + tid];
#pragma unroll 8
        for (int m = 0; m < 64; m++) acc += sR[m * 132 + tid] * sk[m];
        g_v[b * 128 + tid] = acc;
    }
}

// ---------------- k4: Vn = Qxx + Qux^T @ K ----------------
__global__ __launch_bounds__(256) void k4_Vn(int t) {
    int b = blockIdx.y, bx = blockIdx.x, tid = threadIdx.x;
    int ib = (bx >> 1) * 64, jb = (bx & 1) * 64;
    const float* Qub = g_Qu + b * M_ * NT_;
    const float* Kb = g_K + ((size_t)t * B_ + b) * (M_ * N_);
    __shared__ float As[16][64];
    __shared__ float Bs[16][64];
    int tx = tid & 15, ty = tid >> 4;
    float acc[4][4] = {};

    for (int kb = 0; kb < 4; kb++) {
        int k = kb * 16 + ty;
        *(float4*)&As[ty][tx * 4] = *(const float4*)(Qub + k * NT_ + ib + tx * 4);
        *(float4*)&Bs[ty][tx * 4] = *(const float4*)(Kb + k * 128 + jb + tx * 4);
        __syncthreads();
#pragma unroll
        for (int kk = 0; kk < 16; kk++) {
            float4 a = *(float4*)&As[kk][ty * 4];
            float4 bq = *(float4*)&Bs[kk][tx * 4];
            FMA16(a, bq)
        }
        __syncthreads();
    }
    const float* Qxxb = g_Qxx + b * N_ * N_;
    float* Vb = g_V + b * N_ * N_;
#pragma unroll
    for (int i = 0; i < 4; i++) {
        int r = ib + ty * 4 + i, cc = jb + tx * 4;
        float4 q4 = *(const float4*)(Qxxb + r * N_ + cc);
        *(float4*)(Vb + r * N_ + cc) =
            make_float4(acc[i][0] + q4.x, acc[i][1] + q4.y, acc[i][2] + q4.z, acc[i][3] + q4.w);
    }
}

// ---------------- forward rollout ----------------
__global__ __launch_bounds__(256) void kfwd(const float* __restrict__ A,
                                            const float* __restrict__ Bm,
                                            const float* __restrict__ c1,
                                            const float* __restrict__ xinit,
                                            float* __restrict__ out) {
    int b = blockIdx.x, tid = threadIdx.x;
    int warp = tid >> 5, lane = tid & 31;
    __shared__ float sx[128], su[64], sxn[128];
    if (tid < 128) sx[tid] = xinit[b * 128 + tid];
    __syncthreads();

    for (int t = 0; t < 128; t++) {
        size_t bt = (size_t)b * T_ + t;
        const float* Kb = g_K + ((size_t)t * B_ + b) * (M_ * N_);
        const float* kb = g_k + ((size_t)t * B_ + b) * M_;
        for (int r = warp; r < 64; r += 8) {
            const float* kr = Kb + r * 128;
            float s = kr[lane] * sx[lane] + kr[32 + lane] * sx[32 + lane]
                    + kr[64 + lane] * sx[64 + lane] + kr[96 + lane] * sx[96 + lane];
#pragma unroll
            for (int o = 16; o; o >>= 1) s += __shfl_down_sync(0xffffffffu, s, o);
            if (lane == 0) su[r] = s + kb[r];
        }
        if (tid < 128) out[bt * NT_ + tid] = sx[tid];
        __syncthreads();
        if (tid < 64) out[bt * NT_ + 128 + tid] = su[tid];

        const float* Ab = A + bt * (size_t)(N_ * N_);
        const float* Bb = Bm + bt * (size_t)(N_ * M_);
        for (int r = warp; r < 128; r += 8) {
            const float* ar = Ab + r * 128;
            const float* br = Bb + r * 64;
            float s = ar[lane] * sx[lane] + ar[32 + lane] * sx[32 + lane]
                    + ar[64 + lane] * sx[64 + lane] + ar[96 + lane] * sx[96 + lane]
                    + br[lane] * su[lane] + br[32 + lane] * su[32 + lane];
#pragma unroll
            for (int o = 16; o; o >>= 1) s += __shfl_down_sync(0xffffffffu, s, o);
            if (lane == 0) sxn[r] = s + c1[bt * 128 + r];
        }
        __syncthreads();
        if (tid < 128) sx[tid] = sxn[tid];
        __syncthreads();
    }
}

// ---------------- launch ----------------
extern "C" void kernel_launch(void* const* d_in, const int* in_sizes, int n_in,
                              void* d_out, int out_size) {
    const float *A = 0, *Bm = 0, *c1 = 0, *Q = 0, *p = 0, *xinit = 0;
    for (int i = 0; i < n_in; i++) {
        switch (in_sizes[i]) {
            case 67108864:  A = (const float*)d_in[i]; break;      // 32*128*128*128
            case 33554432:  Bm = (const float*)d_in[i]; break;     // 32*128*128*64
            case 524288:    c1 = (const float*)d_in[i]; break;     // 32*128*128
            case 150994944: Q = (const float*)d_in[i]; break;      // 32*128*192*192
            case 786432:    p = (const float*)d_in[i]; break;      // 32*128*192
            case 4096:      xinit = (const float*)d_in[i]; break;  // 32*128
        }
    }
    float* out = (float*)d_out;

    int k3_smem = SM_TOT * (int)sizeof(float);
    cudaFuncSetAttribute(k3_solve, cudaFuncAttributeMaxDynamicSharedMemorySize, k3_smem);

    kzero<<<(B_ * N_ * N_ + 255) / 256, 256>>>();
    for (int t = T_ - 1; t >= 0; t--) {
        k1_VF<<<dim3(7, B_), 256>>>(A, Bm, c1, t);
        k2_Qhat<<<dim3(8, B_), 256>>>(A, Bm, Q, p, t);
        k3_solve<<<B_, 256, k3_smem>>>(t);
        k4_Vn<<<dim3(4, B_), 256>>>(t);
    }
    kfwd<<<B_, 256>>>(A, Bm, c1, xinit, out);
}